// round 3
// baseline (speedup 1.0000x reference)
#include <cuda_runtime.h>

// DilateAttention: B=8, d=768, N=6144, head_dim=32, kernel_size=3
// h=24 heads, g=2048 windows: 393216 independent 3x3 attentions over 32 dims.
// HBM-streaming problem: 604 MB total traffic.
//
// R2 change vs R1 (112.6us): drop the smem output staging + __syncthreads.
// Each thread's 96 output floats are contiguous in gmem (row 3*gi + h/8,
// col (h%8)*96 ...), so we buffer 4 channels in registers and emit STG.128
// directly. This frees all shared memory -> occupancy doubles (16 -> 32+
// warps/SM) and removes the per-block barrier/writeback bubble that drained
// load MLP. Scattered-store L1 wavefront cost (~9.4M) stays under the DRAM
// floor.

namespace {
constexpr int G   = 2048;   // windows per (b,h)
constexpr int NH  = 24;     // heads
constexpr int HD  = 32;     // head_dim
constexpr int NN  = 6144;   // sequence length
constexpr int DD  = 768;    // model dim
constexpr int TPB = 256;
constexpr int NWIN = 8 * NH * G;  // 393216 windows total
}

__global__ __launch_bounds__(TPB)
void dilate_attn_kernel(const float* __restrict__ q,
                        const float* __restrict__ kin,
                        const float* __restrict__ v,
                        float* __restrict__ out)
{
    const int t  = threadIdx.x;
    const int wt = blockIdx.x * TPB + t;     // global window id
    const int gi = wt & (G - 1);
    const int bh = wt >> 11;                 // 2048 = 2^11
    const int h  = bh % NH;
    const int b  = bh / NH;

    // q[b, h*32+c, k*2048+gi]; channel stride NN, window-element stride G.
    // Lanes vary gi -> every 4B load is part of a perfectly coalesced 128B line.
    const int base = (b * DD + h * HD) * NN + gi;
    const float* qp = q   + base;
    const float* kp = kin + base;

    // ---- attn logits: 9 dot products over the 32 channels ----
    float a00=0.f,a01=0.f,a02=0.f,a10=0.f,a11=0.f,a12=0.f,a20=0.f,a21=0.f,a22=0.f;
#pragma unroll
    for (int c = 0; c < HD; ++c) {
        const int off = c * NN;
        float q0 = qp[off], q1 = qp[off + G], q2 = qp[off + 2 * G];
        float k0 = kp[off], k1 = kp[off + G], k2 = kp[off + 2 * G];
        a00 = fmaf(q0, k0, a00); a01 = fmaf(q0, k1, a01); a02 = fmaf(q0, k2, a02);
        a10 = fmaf(q1, k0, a10); a11 = fmaf(q1, k1, a11); a12 = fmaf(q1, k2, a12);
        a20 = fmaf(q2, k0, a20); a21 = fmaf(q2, k1, a21); a22 = fmaf(q2, k2, a22);
    }

    // ---- softmax over each 3-row (scale folded in before exp) ----
    const float sc = 0.17677669529663687f;  // 1/sqrt(32)
    float m0 = fmaxf(fmaxf(a00, a01), a02);
    float m1 = fmaxf(fmaxf(a10, a11), a12);
    float m2 = fmaxf(fmaxf(a20, a21), a22);
    float e00 = __expf((a00 - m0) * sc), e01 = __expf((a01 - m0) * sc), e02 = __expf((a02 - m0) * sc);
    float e10 = __expf((a10 - m1) * sc), e11 = __expf((a11 - m1) * sc), e12 = __expf((a12 - m1) * sc);
    float e20 = __expf((a20 - m2) * sc), e21 = __expf((a21 - m2) * sc), e22 = __expf((a22 - m2) * sc);
    float r0 = 1.f / (e00 + e01 + e02);
    float r1 = 1.f / (e10 + e11 + e12);
    float r2 = 1.f / (e20 + e21 + e22);
    float p00 = e00 * r0, p01 = e01 * r0, p02 = e02 * r0;
    float p10 = e10 * r1, p11 = e11 * r1, p12 = e12 * r1;
    float p20 = e20 * r2, p21 = e21 * r2, p22 = e22 * r2;

    // ---- output = attn @ v, written directly as float4 ----
    // Output element (k, c) of this window lives at ob[k*32 + c]; the 96
    // floats are contiguous (384B, 16B-aligned: (h&7)*96 floats = 384B).
    const float* vp = v + base;
    float* ob = out + ((size_t)(b * NN + gi * 3 + (h >> 3))) * DD + (h & 7) * 96;

#pragma unroll
    for (int cg = 0; cg < HD; cg += 4) {
        float4 o0, o1, o2;
        float* o0p = &o0.x; float* o1p = &o1.x; float* o2p = &o2.x;
#pragma unroll
        for (int j = 0; j < 4; ++j) {
            const int off = (cg + j) * NN;
            float v0 = vp[off], v1 = vp[off + G], v2 = vp[off + 2 * G];
            o0p[j] = fmaf(p00, v0, fmaf(p01, v1, p02 * v2));
            o1p[j] = fmaf(p10, v0, fmaf(p11, v1, p12 * v2));
            o2p[j] = fmaf(p20, v0, fmaf(p21, v1, p22 * v2));
        }
        *reinterpret_cast<float4*>(ob + cg)      = o0;
        *reinterpret_cast<float4*>(ob + 32 + cg) = o1;
        *reinterpret_cast<float4*>(ob + 64 + cg) = o2;
    }
}

extern "C" void kernel_launch(void* const* d_in, const int* in_sizes, int n_in,
                              void* d_out, int out_size)
{
    const float* q = (const float*)d_in[0];
    const float* k = (const float*)d_in[1];
    const float* v = (const float*)d_in[2];
    float* out = (float*)d_out;
    dilate_attn_kernel<<<NWIN / TPB, TPB>>>(q, k, v, out);
}